// round 16
// baseline (speedup 1.0000x reference)
#include <cuda_runtime.h>
#include <cuda_bf16.h>

// HeadWise_JSD: out = (0.5/12) * sum p * (log p - log q)   [kl_pm == 0 exactly]
// Streaming reduction over 2 x 201 MB fp32.
// Champion config (48 w/SM, 4-deep LDG.128.CS batch, 36-reg schedule,
// 888 blocks = one wave, 6.74 TB/s) kept bit-identical in the main loop.
// R16: fold the zero-kernel into the main kernel with a minimal fused
// epilogue (device-global atomic accumulator + last-block finalize),
// removing one serialized graph node (~1-2 us).

static __device__ __forceinline__ float term(float p, float q) {
    // p * lg2(p/q): MUFU.RCP + FMUL + MUFU.LG2 + FMUL; ~1e-5 worst-case rel.
    float r = __fdividef(p, q);
    return p * __log2f(r);
}

static __device__ __forceinline__ float term4(float4 pv, float4 qv) {
    float a = term(pv.x, qv.x) + term(pv.y, qv.y);
    float b = term(pv.z, qv.z) + term(pv.w, qv.w);
    return a + b;
}

__device__ float        g_acc  = 0.0f;   // self-resetting accumulator
__device__ unsigned int g_done = 0;      // self-resetting done counter

__global__ __launch_bounds__(256, 6) void jsd_reduce_kernel(
    const float4* __restrict__ p4,
    const float4* __restrict__ q4,
    float* __restrict__ out,
    int n4)
{
    const int stride = gridDim.x * 256;
    int i = blockIdx.x * 256 + threadIdx.x;

    float a0 = 0.0f, a1 = 0.0f;

    // 4 front-batched streaming LDG.128.CS per macro-iter (proven optimum:
    // 48 warps/SM x 4 lines each, 36-reg schedule).
    for (; i + stride < n4; i += 2 * stride) {
        float4 p0 = __ldcs(p4 + i);
        float4 p1 = __ldcs(p4 + i + stride);
        float4 q0 = __ldcs(q4 + i);
        float4 q1 = __ldcs(q4 + i + stride);
        a0 += term4(p0, q0);
        a1 += term4(p1, q1);
    }
    for (; i < n4; i += stride)
        a0 += term4(__ldcs(p4 + i), __ldcs(q4 + i));

    // log2-units -> nats
    float acc = (a0 + a1) * 0.69314718055994531f;

    #pragma unroll
    for (int o = 16; o; o >>= 1)
        acc += __shfl_xor_sync(0xffffffffu, acc, o);

    __shared__ float smem[8];
    __shared__ bool  is_last;
    int lane = threadIdx.x & 31;
    int warp = threadIdx.x >> 5;
    if (lane == 0) smem[warp] = acc;
    __syncthreads();

    if (warp == 0) {
        float v = (lane < 8) ? smem[lane] : 0.0f;
        #pragma unroll
        for (int o = 4; o; o >>= 1)
            v += __shfl_xor_sync(0xffffffffu, v, o);
        if (lane == 0) {
            atomicAdd(&g_acc, v);
            __threadfence();
            unsigned int t = atomicAdd(&g_done, 1u);
            is_last = (t == gridDim.x - 1);
        }
    }
    __syncthreads();

    // last block: all prior adds are visible (each block fenced between its
    // add and its done-increment). Write scaled result, reset globals.
    if (is_last && threadIdx.x == 0) {
        __threadfence();
        float s = *(volatile float*)&g_acc;
        out[0]  = s * (0.5f / 12.0f);
        *(volatile float*)&g_acc = 0.0f;       // reset for next graph replay
        __threadfence();
        *(volatile unsigned int*)&g_done = 0u;
    }
}

extern "C" void kernel_launch(void* const* d_in, const int* in_sizes, int n_in,
                              void* d_out, int out_size) {
    const float4* p4 = (const float4*)d_in[0];
    const float4* q4 = (const float4*)d_in[1];
    float* out = (float*)d_out;

    int n  = in_sizes[0];     // 1024*12*4096
    int n4 = n >> 2;          // 12,582,912 float4 pairs

    // single launch: 148 SMs x 6 blocks = 888 blocks, one full wave
    jsd_reduce_kernel<<<888, 256>>>(p4, q4, out, n4);
}

// round 17
// speedup vs baseline: 1.0066x; 1.0066x over previous
#include <cuda_runtime.h>
#include <cuda_bf16.h>

// HeadWise_JSD: out = (0.5/12) * sum p * (log p - log q)   [kl_pm == 0 exactly,
// since m = log(0.5*(p+p)) == log(p) bit-exactly].
// Streaming reduction over 2 x 201 MB fp32.
//
// FINAL — champion config after exhaustive sweep (best measured 61.9us,
// 6.74 TB/s = 84% of spec HBM):
//   - 48 warps/SM: 6 blocks x 256 thr, 888 blocks = exactly one wave
//   - 4-deep front-batched LDG.128.CS (36-reg schedule; deeper batches and
//     other reg budgets measured slower)
//   - light math: 2 MUFU + 2 FMUL per element via p * lg2(p/q)
//   - grid-stride addressing (contiguous chunks measured slower)
//   - two launches (fused atomic finalize measured equal; this is simpler)
// Swept and rejected: 32/56/64 warps, 6/8-deep batches, 32/40-reg codegen,
// TMA bulk pipeline, contiguous-chunk addressing, fused single-launch.

static __device__ __forceinline__ float term(float p, float q) {
    // p * lg2(p/q): MUFU.RCP + FMUL + MUFU.LG2 + FMUL. abs err ~2^-22/op,
    // weighted by sum(p)=12288 vs output O(250) -> ~1e-5 worst-case rel.
    float r = __fdividef(p, q);
    return p * __log2f(r);
}

static __device__ __forceinline__ float term4(float4 pv, float4 qv) {
    float a = term(pv.x, qv.x) + term(pv.y, qv.y);
    float b = term(pv.z, qv.z) + term(pv.w, qv.w);
    return a + b;
}

__global__ void jsd_zero_kernel(float* out) {
    if (threadIdx.x == 0 && blockIdx.x == 0) out[0] = 0.0f;
}

__global__ __launch_bounds__(256, 6) void jsd_reduce_kernel(
    const float4* __restrict__ p4,
    const float4* __restrict__ q4,
    float* __restrict__ out,
    int n4)
{
    const int stride = gridDim.x * 256;
    int i = blockIdx.x * 256 + threadIdx.x;

    float a0 = 0.0f, a1 = 0.0f;

    // 4 front-batched streaming LDG.128.CS per macro-iter; chip-level MLP
    // from 48 warps/SM x 4 lines each (the measured optimum).
    for (; i + stride < n4; i += 2 * stride) {
        float4 p0 = __ldcs(p4 + i);
        float4 p1 = __ldcs(p4 + i + stride);
        float4 q0 = __ldcs(q4 + i);
        float4 q1 = __ldcs(q4 + i + stride);
        a0 += term4(p0, q0);
        a1 += term4(p1, q1);
    }
    for (; i < n4; i += stride)
        a0 += term4(__ldcs(p4 + i), __ldcs(q4 + i));

    // log2-units -> nats
    float acc = (a0 + a1) * 0.69314718055994531f;

    #pragma unroll
    for (int o = 16; o; o >>= 1)
        acc += __shfl_xor_sync(0xffffffffu, acc, o);

    __shared__ float smem[8];
    int lane = threadIdx.x & 31;
    int warp = threadIdx.x >> 5;
    if (lane == 0) smem[warp] = acc;
    __syncthreads();

    if (warp == 0) {
        float v = (lane < 8) ? smem[lane] : 0.0f;
        #pragma unroll
        for (int o = 4; o; o >>= 1)
            v += __shfl_xor_sync(0xffffffffu, v, o);
        if (lane == 0)
            atomicAdd(out, v * (0.5f / 12.0f));
    }
}

extern "C" void kernel_launch(void* const* d_in, const int* in_sizes, int n_in,
                              void* d_out, int out_size) {
    const float4* p4 = (const float4*)d_in[0];
    const float4* q4 = (const float4*)d_in[1];
    float* out = (float*)d_out;

    int n  = in_sizes[0];     // 1024*12*4096
    int n4 = n >> 2;          // 12,582,912 float4 pairs

    jsd_zero_kernel<<<1, 32>>>(out);

    // 148 SMs x 6 blocks = 888 blocks: one full wave at 48 warps/SM
    jsd_reduce_kernel<<<888, 256>>>(p4, q4, out, n4);
}